// round 1
// baseline (speedup 1.0000x reference)
#include <cuda_runtime.h>
#include <cuda_bf16.h>
#include <mma.h>

using namespace nvcuda;

#define D_MODEL     2048
#define NUM_CLASSES 50257
#define NB          8
#define RANK        4
#define HIDDEN      128
#define BATCH       2048
#define LN_EPS      1e-5f

// u[b][k] with k = n*RANK + r  (rank-32 fused LoRA operand)
__device__ float g_u[BATCH * 32];

// ---------------------------------------------------------------------------
// Prep kernel: ctx MLP -> LN -> GELU -> coeffs -> y -> z -> u  (all fp32)
// One block handles 16 batch rows. 256 threads.
// ---------------------------------------------------------------------------
__global__ __launch_bounds__(256) void prep_kernel(
    const float* __restrict__ x, const float* __restrict__ context,
    const float* __restrict__ ctx_w, const float* __restrict__ ctx_b,
    const float* __restrict__ ln_g, const float* __restrict__ ln_b,
    const float* __restrict__ coeff_w, const float* __restrict__ coeff_b,
    const float* __restrict__ basis_A)
{
    __shared__ float h_sh[16][HIDDEN];
    __shared__ float coeffs_sh[16][NB];
    __shared__ float y_sh[16][32];
    __shared__ float z_sh[16][RANK];

    const int t  = threadIdx.x;
    const int r0 = blockIdx.x * 16;

    // Phase A: h0 = context @ ctx_w^T + ctx_b   (16 x 128 dots of length 2048)
    #pragma unroll 1
    for (int i = 0; i < 8; i++) {
        int idx = t + 256 * i;          // 0..2047
        int row = idx >> 7;
        int h   = idx & 127;
        const float4* cp = reinterpret_cast<const float4*>(context + (size_t)(r0 + row) * D_MODEL);
        const float4* wp = reinterpret_cast<const float4*>(ctx_w   + (size_t)h * D_MODEL);
        float a0 = 0.f, a1 = 0.f, a2 = 0.f, a3 = 0.f;
        #pragma unroll 4
        for (int k = 0; k < D_MODEL / 4; k++) {
            float4 a = cp[k];
            float4 b = wp[k];
            a0 += a.x * b.x; a1 += a.y * b.y; a2 += a.z * b.z; a3 += a.w * b.w;
        }
        h_sh[row][h] = (a0 + a1) + (a2 + a3) + ctx_b[h];
    }
    __syncthreads();

    // Phase B: LayerNorm + exact GELU (one warp per 2 rows)
    {
        const int lane = t & 31;
        const int w    = t >> 5;
        #pragma unroll
        for (int rr = 0; rr < 2; rr++) {
            int row = w * 2 + rr;
            float v[4];
            float s = 0.f;
            #pragma unroll
            for (int j = 0; j < 4; j++) { v[j] = h_sh[row][lane * 4 + j]; s += v[j]; }
            #pragma unroll
            for (int o = 16; o > 0; o >>= 1) s += __shfl_xor_sync(0xffffffffu, s, o);
            float mu = s * (1.0f / HIDDEN);
            float q = 0.f;
            #pragma unroll
            for (int j = 0; j < 4; j++) { float d = v[j] - mu; q += d * d; }
            #pragma unroll
            for (int o = 16; o > 0; o >>= 1) q += __shfl_xor_sync(0xffffffffu, q, o);
            float rstd = rsqrtf(q * (1.0f / HIDDEN) + LN_EPS);
            #pragma unroll
            for (int j = 0; j < 4; j++) {
                int c = lane * 4 + j;
                float hn = (v[j] - mu) * rstd * ln_g[c] + ln_b[c];
                // exact GELU: 0.5*x*(1+erf(x/sqrt(2)))
                h_sh[row][c] = 0.5f * hn * (1.0f + erff(hn * 0.7071067811865475f));
            }
        }
    }
    __syncthreads();

    // Phase C: coeffs = h @ coeff_w^T + coeff_b   (16 x 8 dots of length 128)
    if (t < 128) {
        int row = t >> 3;
        int n   = t & 7;
        const float* wp = coeff_w + (size_t)n * HIDDEN;
        float acc = coeff_b[n];
        #pragma unroll 8
        for (int j = 0; j < HIDDEN; j++) acc += h_sh[row][j] * wp[j];
        coeffs_sh[row][n] = acc;
    }

    // Phase D: y[row][k] = dot(x[row], basis_A[k])  for k = n*RANK+r, 32 rows of A
    #pragma unroll 1
    for (int i = 0; i < 2; i++) {
        int idx = t + 256 * i;          // 0..511
        int row = idx >> 5;
        int k   = idx & 31;
        const float4* xp = reinterpret_cast<const float4*>(x       + (size_t)(r0 + row) * D_MODEL);
        const float4* ap = reinterpret_cast<const float4*>(basis_A + (size_t)k * D_MODEL);
        float a0 = 0.f, a1 = 0.f, a2 = 0.f, a3 = 0.f;
        #pragma unroll 4
        for (int kk = 0; kk < D_MODEL / 4; kk++) {
            float4 a = xp[kk];
            float4 b = ap[kk];
            a0 += a.x * b.x; a1 += a.y * b.y; a2 += a.z * b.z; a3 += a.w * b.w;
        }
        y_sh[row][k] = (a0 + a1) + (a2 + a3);
    }
    __syncthreads();

    // Phase E: z[row][r] = sum_n coeffs[row][n] * y[row][n*RANK+r]
    if (t < 64) {
        int row = t >> 2;
        int r   = t & 3;
        float acc = 0.f;
        #pragma unroll
        for (int n = 0; n < NB; n++) acc += coeffs_sh[row][n] * y_sh[row][n * RANK + r];
        z_sh[row][r] = acc;
    }
    __syncthreads();

    // Phase F: u[row][n*RANK+r] = coeffs[row][n] * z[row][r]  -> global
    #pragma unroll
    for (int i = 0; i < 2; i++) {
        int idx = t + 256 * i;
        int row = idx >> 5;
        int k   = idx & 31;
        g_u[(size_t)(r0 + row) * 32 + k] = coeffs_sh[row][k >> 2] * z_sh[row][k & 3];
    }
}

// ---------------------------------------------------------------------------
// Main fused GEMM: out[b][c] = x[b]·W[c] + base_b[c] + u[b]·Bt[:,c]
// Split-bf16 (3-term) emulated fp32 via wmma 16x16x16 bf16.
// Block tile 128x128, K-chunk 32, 8 warps each computing a 64x32 warp tile.
// ---------------------------------------------------------------------------
#define BM 128
#define BN 128
#define BK 32
#define LDSH 40   // bf16 elements per smem row (80B, multiple of 16B)

__device__ __forceinline__ void split_store(__nv_bfloat16* hi, __nv_bfloat16* lo, float4 v)
{
    float f[4] = {v.x, v.y, v.z, v.w};
    __nv_bfloat16 h[4], l[4];
    #pragma unroll
    for (int j = 0; j < 4; j++) {
        h[j] = __float2bfloat16(f[j]);
        l[j] = __float2bfloat16(f[j] - __bfloat162float(h[j]));
    }
    __nv_bfloat162 ph0, ph1, pl0, pl1;
    ph0.x = h[0]; ph0.y = h[1]; ph1.x = h[2]; ph1.y = h[3];
    pl0.x = l[0]; pl0.y = l[1]; pl1.x = l[2]; pl1.y = l[3];
    reinterpret_cast<__nv_bfloat162*>(hi)[0] = ph0;
    reinterpret_cast<__nv_bfloat162*>(hi)[1] = ph1;
    reinterpret_cast<__nv_bfloat162*>(lo)[0] = pl0;
    reinterpret_cast<__nv_bfloat162*>(lo)[1] = pl1;
}

__global__ __launch_bounds__(256, 2) void main_kernel(
    const float* __restrict__ x, const float* __restrict__ base_w,
    const float* __restrict__ base_b, const float* __restrict__ basis_B,
    float* __restrict__ out)
{
    __shared__ alignas(128) unsigned char smem_raw[4 * BM * LDSH * 2]; // 40960 B

    __nv_bfloat16* As_hi = reinterpret_cast<__nv_bfloat16*>(smem_raw);
    __nv_bfloat16* As_lo = As_hi + BM * LDSH;
    __nv_bfloat16* Bs_hi = As_lo + BM * LDSH;
    __nv_bfloat16* Bs_lo = Bs_hi + BN * LDSH;

    const int t    = threadIdx.x;
    const int warp = t >> 5;
    const int lane = t & 31;
    const int b0   = blockIdx.x * BM;   // batch tile (16)
    const int c0   = blockIdx.y * BN;   // class tile (393)

    const int wr = warp >> 2;   // 0..1  -> 64 rows each
    const int wc = warp & 3;    // 0..3  -> 32 cols each

    wmma::fragment<wmma::accumulator, 16, 16, 16, float> acc[4][2];
    #pragma unroll
    for (int i = 0; i < 4; i++)
        #pragma unroll
        for (int j = 0; j < 2; j++)
            wmma::fill_fragment(acc[i][j], 0.0f);

    const int NCHUNK = D_MODEL / BK;    // 64 regular chunks + 1 LoRA chunk

    for (int ch = 0; ch <= NCHUNK; ch++) {
        __syncthreads();
        if (ch < NCHUNK) {
            const int k0 = ch * BK;
            // A tile: x[b0..b0+127][k0..k0+31]
            #pragma unroll
            for (int it = 0; it < 4; it++) {
                int idx = t + 256 * it;
                int m = idx >> 3, kq = idx & 7;
                float4 v = *reinterpret_cast<const float4*>(x + (size_t)(b0 + m) * D_MODEL + k0 + kq * 4);
                split_store(As_hi + m * LDSH + kq * 4, As_lo + m * LDSH + kq * 4, v);
            }
            // B tile: base_w[c0..c0+127][k0..k0+31]  (guard c)
            #pragma unroll
            for (int it = 0; it < 4; it++) {
                int idx = t + 256 * it;
                int cc = idx >> 3, kq = idx & 7;
                float4 v = make_float4(0.f, 0.f, 0.f, 0.f);
                if (c0 + cc < NUM_CLASSES)
                    v = *reinterpret_cast<const float4*>(base_w + (size_t)(c0 + cc) * D_MODEL + k0 + kq * 4);
                split_store(Bs_hi + cc * LDSH + kq * 4, Bs_lo + cc * LDSH + kq * 4, v);
            }
        } else {
            // LoRA chunk: A = u (128x32), B = Bt[k][c] = basis_B[k>>2][c][k&3]
            #pragma unroll
            for (int it = 0; it < 4; it++) {
                int idx = t + 256 * it;
                int m = idx >> 3, kq = idx & 7;
                float4 v = *reinterpret_cast<const float4*>(g_u + (size_t)(b0 + m) * 32 + kq * 4);
                split_store(As_hi + m * LDSH + kq * 4, As_lo + m * LDSH + kq * 4, v);
            }
            #pragma unroll
            for (int it = 0; it < 4; it++) {
                int idx = t + 256 * it;
                int cc = idx >> 3, kq = idx & 7;   // kq = basis index n; float4 = r0..r3
                float4 v = make_float4(0.f, 0.f, 0.f, 0.f);
                if (c0 + cc < NUM_CLASSES)
                    v = *reinterpret_cast<const float4*>(basis_B + ((size_t)kq * NUM_CLASSES + (c0 + cc)) * 4);
                split_store(Bs_hi + cc * LDSH + kq * 4, Bs_lo + cc * LDSH + kq * 4, v);
            }
        }
        __syncthreads();

        #pragma unroll
        for (int kk = 0; kk < BK; kk += 16) {
            wmma::fragment<wmma::matrix_b, 16, 16, 16, __nv_bfloat16, wmma::col_major> bh[2], bl[2];
            #pragma unroll
            for (int j = 0; j < 2; j++) {
                int cb = wc * 32 + j * 16;
                wmma::load_matrix_sync(bh[j], Bs_hi + cb * LDSH + kk, LDSH);
                wmma::load_matrix_sync(bl[j], Bs_lo + cb * LDSH + kk, LDSH);
            }
            #pragma unroll
            for (int i = 0; i < 4; i++) {
                wmma::fragment<wmma::matrix_a, 16, 16, 16, __nv_bfloat16, wmma::row_major> ah, al;
                int mb = wr * 64 + i * 16;
                wmma::load_matrix_sync(ah, As_hi + mb * LDSH + kk, LDSH);
                wmma::load_matrix_sync(al, As_lo + mb * LDSH + kk, LDSH);
                #pragma unroll
                for (int j = 0; j < 2; j++) {
                    wmma::mma_sync(acc[i][j], ah, bh[j], acc[i][j]);  // hi*hi
                    wmma::mma_sync(acc[i][j], ah, bl[j], acc[i][j]);  // hi*lo
                    wmma::mma_sync(acc[i][j], al, bh[j], acc[i][j]);  // lo*hi
                }
            }
        }
    }

    __syncthreads();  // smem tiles no longer needed; reuse as per-warp C bounce

    float* cbuf = reinterpret_cast<float*>(smem_raw) + warp * (16 * 20);
    #pragma unroll
    for (int i = 0; i < 4; i++) {
        #pragma unroll
        for (int j = 0; j < 2; j++) {
            wmma::store_matrix_sync(cbuf, acc[i][j], 20, wmma::mem_row_major);
            __syncwarp();
            int mb = b0 + wr * 64 + i * 16;
            int cb = c0 + wc * 32 + j * 16;
            #pragma unroll
            for (int e = 0; e < 8; e++) {
                int idx = lane + 32 * e;        // 0..255
                int rr = idx >> 4, cc = idx & 15;
                int c = cb + cc;
                if (c < NUM_CLASSES)
                    out[(size_t)(mb + rr) * NUM_CLASSES + c] = cbuf[rr * 20 + cc] + __ldg(base_b + c);
            }
            __syncwarp();
        }
    }
}

// ---------------------------------------------------------------------------
extern "C" void kernel_launch(void* const* d_in, const int* in_sizes, int n_in,
                              void* d_out, int out_size)
{
    const float* x       = (const float*)d_in[0];
    const float* context = (const float*)d_in[1];
    const float* base_w  = (const float*)d_in[2];
    const float* base_b  = (const float*)d_in[3];
    const float* ctx_w   = (const float*)d_in[4];
    const float* ctx_b   = (const float*)d_in[5];
    const float* ln_g    = (const float*)d_in[6];
    const float* ln_b    = (const float*)d_in[7];
    const float* coeff_w = (const float*)d_in[8];
    const float* coeff_b = (const float*)d_in[9];
    const float* basis_A = (const float*)d_in[10];
    const float* basis_B = (const float*)d_in[11];
    float* out = (float*)d_out;

    (void)in_sizes; (void)n_in; (void)out_size;

    prep_kernel<<<BATCH / 16, 256>>>(x, context, ctx_w, ctx_b, ln_g, ln_b,
                                     coeff_w, coeff_b, basis_A);

    dim3 grid(BATCH / BM, (NUM_CLASSES + BN - 1) / BN);  // m inner, c outer -> L2 reuse of base_w
    main_kernel<<<grid, 256>>>(x, base_w, base_b, basis_B, out);
}

// round 3
// speedup vs baseline: 1.2889x; 1.2889x over previous
#include <cuda_runtime.h>
#include <cuda_fp16.h>
#include <mma.h>
#include <cstdint>

using namespace nvcuda;

#define D_MODEL     2048
#define NUM_CLASSES 50257
#define NB          8
#define RANK        4
#define HIDDEN      128
#define BATCH       2048
#define LN_EPS      1e-5f

#define KTOT   2112                 // 2048 (x|w) + 32 (LoRA u|Bt) + 32 zero pad
#define BK     64                   // K per pipeline stage
#define KT     (KTOT / BK)          // 33 stages per pass
#define NST    (2 * KT)             // 66 total (pass0: Whi, pass1: Wlo)

#define BM 128
#define BN 128
#define LDSH 72                     // fp16 elems per smem row (144B, 16B-mult, conflict-free)
#define STAGE_ELEMS (128 * LDSH)    // per A or B tile
#define STAGE_BYTES (STAGE_ELEMS * 2)
#define SMEM_TOTAL  (3 * 2 * STAGE_BYTES)   // 110592 B

// ---------------- device scratch ----------------
__device__ float  g_u[BATCH * 32];
__device__ __half g_Xh [(size_t)BATCH       * KTOT];
__device__ __half g_Whi[(size_t)NUM_CLASSES * KTOT];
__device__ __half g_Wlo[(size_t)NUM_CLASSES * KTOT];

__device__ __forceinline__ uint32_t smem_u32(const void* p) {
    uint32_t a;
    asm("{ .reg .u64 t; cvta.to.shared.u64 t, %1; cvt.u32.u64 %0, t; }" : "=r"(a) : "l"(p));
    return a;
}
#define CP_ASYNC16(dst, src) \
    asm volatile("cp.async.cg.shared.global [%0], [%1], 16;" :: "r"(dst), "l"(src))
#define CP_COMMIT() asm volatile("cp.async.commit_group;" ::: "memory")
#define CP_WAIT(n)  asm volatile("cp.async.wait_group %0;" :: "n"(n) : "memory")

// ---------------------------------------------------------------------------
// prep_ctx: ctx MLP -> LN -> GELU -> coeffs -> z -> u  (fp32, 16 rows / block)
// ---------------------------------------------------------------------------
__global__ __launch_bounds__(256) void prep_ctx(
    const float* __restrict__ x, const float* __restrict__ context,
    const float* __restrict__ ctx_w, const float* __restrict__ ctx_b,
    const float* __restrict__ ln_g, const float* __restrict__ ln_b,
    const float* __restrict__ coeff_w, const float* __restrict__ coeff_b,
    const float* __restrict__ basis_A)
{
    __shared__ float h_sh[16][HIDDEN];
    __shared__ float coeffs_sh[16][NB];
    __shared__ float y_sh[16][32];
    __shared__ float z_sh[16][RANK];

    const int t  = threadIdx.x;
    const int r0 = blockIdx.x * 16;

    #pragma unroll 1
    for (int i = 0; i < 8; i++) {
        int idx = t + 256 * i;
        int row = idx >> 7, h = idx & 127;
        const float4* cp = reinterpret_cast<const float4*>(context + (size_t)(r0 + row) * D_MODEL);
        const float4* wp = reinterpret_cast<const float4*>(ctx_w + (size_t)h * D_MODEL);
        float a0 = 0.f, a1 = 0.f, a2 = 0.f, a3 = 0.f;
        #pragma unroll 4
        for (int k = 0; k < D_MODEL / 4; k++) {
            float4 a = cp[k]; float4 b = wp[k];
            a0 += a.x * b.x; a1 += a.y * b.y; a2 += a.z * b.z; a3 += a.w * b.w;
        }
        h_sh[row][h] = (a0 + a1) + (a2 + a3) + ctx_b[h];
    }
    __syncthreads();

    {
        const int lane = t & 31, w = t >> 5;
        #pragma unroll
        for (int rr = 0; rr < 2; rr++) {
            int row = w * 2 + rr;
            float v[4]; float s = 0.f;
            #pragma unroll
            for (int j = 0; j < 4; j++) { v[j] = h_sh[row][lane * 4 + j]; s += v[j]; }
            #pragma unroll
            for (int o = 16; o > 0; o >>= 1) s += __shfl_xor_sync(0xffffffffu, s, o);
            float mu = s * (1.0f / HIDDEN);
            float q = 0.f;
            #pragma unroll
            for (int j = 0; j < 4; j++) { float d = v[j] - mu; q += d * d; }
            #pragma unroll
            for (int o = 16; o > 0; o >>= 1) q += __shfl_xor_sync(0xffffffffu, q, o);
            float rstd = rsqrtf(q * (1.0f / HIDDEN) + LN_EPS);
            #pragma unroll
            for (int j = 0; j < 4; j++) {
                int c = lane * 4 + j;
                float hn = (v[j] - mu) * rstd * ln_g[c] + ln_b[c];
                h_sh[row][c] = 0.5f * hn * (1.0f + erff(hn * 0.7071067811865475f));
            }
        }
    }
    __syncthreads();

    if (t < 128) {
        int row = t >> 3, n = t & 7;
        const float* wp = coeff_w + (size_t)n * HIDDEN;
        float acc = coeff_b[n];
        #pragma unroll 8
        for (int j = 0; j < HIDDEN; j++) acc += h_sh[row][j] * wp[j];
        coeffs_sh[row][n] = acc;
    }

    #pragma unroll 1
    for (int i = 0; i < 2; i++) {
        int idx = t + 256 * i;
        int row = idx >> 5, k = idx & 31;
        const float4* xp = reinterpret_cast<const float4*>(x + (size_t)(r0 + row) * D_MODEL);
        const float4* ap = reinterpret_cast<const float4*>(basis_A + (size_t)k * D_MODEL);
        float a0 = 0.f, a1 = 0.f, a2 = 0.f, a3 = 0.f;
        #pragma unroll 4
        for (int kk = 0; kk < D_MODEL / 4; kk++) {
            float4 a = xp[kk]; float4 b = ap[kk];
            a0 += a.x * b.x; a1 += a.y * b.y; a2 += a.z * b.z; a3 += a.w * b.w;
        }
        y_sh[row][k] = (a0 + a1) + (a2 + a3);
    }
    __syncthreads();

    if (t < 64) {
        int row = t >> 2, r = t & 3;
        float acc = 0.f;
        #pragma unroll
        for (int n = 0; n < NB; n++) acc += coeffs_sh[row][n] * y_sh[row][n * RANK + r];
        z_sh[row][r] = acc;
    }
    __syncthreads();

    #pragma unroll
    for (int i = 0; i < 2; i++) {
        int idx = t + 256 * i;
        int row = idx >> 5, k = idx & 31;
        g_u[(size_t)(r0 + row) * 32 + k] = coeffs_sh[row][k >> 2] * z_sh[row][k & 3];
    }
}

// ---------------------------------------------------------------------------
// convert_x: g_Xh[b][0:2048]=fp16(x), [2048:2080]=fp16(u), rest 0
// ---------------------------------------------------------------------------
__global__ __launch_bounds__(256) void convert_x(const float* __restrict__ x)
{
    size_t i = (size_t)blockIdx.x * 256 + threadIdx.x;          // one per 8 elems
    if (i >= (size_t)BATCH * (KTOT / 8)) return;
    int row = (int)(i / (KTOT / 8));
    int k0  = (int)(i % (KTOT / 8)) * 8;

    float v[8];
    if (k0 < D_MODEL) {
        const float4* p = reinterpret_cast<const float4*>(x + (size_t)row * D_MODEL + k0);
        float4 a = p[0], b = p[1];
        v[0]=a.x; v[1]=a.y; v[2]=a.z; v[3]=a.w; v[4]=b.x; v[5]=b.y; v[6]=b.z; v[7]=b.w;
    } else if (k0 < D_MODEL + 32) {
        #pragma unroll
        for (int j = 0; j < 8; j++) v[j] = g_u[(size_t)row * 32 + (k0 - D_MODEL) + j];
    } else {
        #pragma unroll
        for (int j = 0; j < 8; j++) v[j] = 0.f;
    }
    union { __half h[8]; uint4 u; } H;
    #pragma unroll
    for (int j = 0; j < 8; j++) H.h[j] = __float2half_rn(v[j]);
    *reinterpret_cast<uint4*>(&g_Xh[(size_t)row * KTOT + k0]) = H.u;
}

// ---------------------------------------------------------------------------
// convert_w: g_Whi = fp16(w), g_Wlo = fp16(w - fp16(w)); LoRA Bt appended at k>=2048
// ---------------------------------------------------------------------------
__global__ __launch_bounds__(256) void convert_w(
    const float* __restrict__ base_w, const float* __restrict__ basis_B)
{
    size_t i = (size_t)blockIdx.x * 256 + threadIdx.x;
    if (i >= (size_t)NUM_CLASSES * (KTOT / 8)) return;
    int row = (int)(i / (KTOT / 8));
    int k0  = (int)(i % (KTOT / 8)) * 8;

    float v[8];
    if (k0 < D_MODEL) {
        const float4* p = reinterpret_cast<const float4*>(base_w + (size_t)row * D_MODEL + k0);
        float4 a = p[0], b = p[1];
        v[0]=a.x; v[1]=a.y; v[2]=a.z; v[3]=a.w; v[4]=b.x; v[5]=b.y; v[6]=b.z; v[7]=b.w;
    } else if (k0 < D_MODEL + 32) {
        #pragma unroll
        for (int j = 0; j < 8; j++) {
            int k = (k0 - D_MODEL) + j;      // n*RANK + r
            v[j] = basis_B[(((size_t)(k >> 2)) * NUM_CLASSES + row) * RANK + (k & 3)];
        }
    } else {
        #pragma unroll
        for (int j = 0; j < 8; j++) v[j] = 0.f;
    }
    union { __half h[8]; uint4 u; } Hi, Lo;
    #pragma unroll
    for (int j = 0; j < 8; j++) {
        __half h = __float2half_rn(v[j]);
        Hi.h[j] = h;
        Lo.h[j] = __float2half_rn(v[j] - __half2float(h));
    }
    size_t off = (size_t)row * KTOT + k0;
    *reinterpret_cast<uint4*>(&g_Whi[off]) = Hi.u;
    *reinterpret_cast<uint4*>(&g_Wlo[off]) = Lo.u;
}

// ---------------------------------------------------------------------------
// Main GEMM: out[b][c] = Xh[b]·(Whi[c]+Wlo[c]) + base_b[c]
// 128x128 tile, 8 warps (64x32 warp tiles), BK=64, 3-stage cp.async pipeline.
// ---------------------------------------------------------------------------
__global__ __launch_bounds__(256, 2) void main_gemm(
    const float* __restrict__ base_b, float* __restrict__ out)
{
    extern __shared__ __align__(128) __half smem[];
    const uint32_t sbase = smem_u32(smem);

    const int t    = threadIdx.x;
    const int warp = t >> 5;
    const int lane = t & 31;
    const int b0   = blockIdx.x * BM;
    const int c0   = blockIdx.y * BN;

    const int wr = warp >> 2;   // 0..1 (64 rows)
    const int wc = warp & 3;    // 0..3 (32 cols)

    // stage s: A at s*(2*STAGE_ELEMS), B at that + STAGE_ELEMS
    auto issue = [&](int s) {
        if (s >= NST) return;
        int pass = (s >= KT);
        int k0   = (s - pass * KT) * BK;
        const __half* Ag = g_Xh + (size_t)b0 * KTOT + k0;
        const __half* Wg = (pass ? g_Wlo : g_Whi);
        int slot = s % 3;
        uint32_t abase = sbase + slot * (2 * STAGE_BYTES);
        uint32_t bbase = abase + STAGE_BYTES;
        #pragma unroll
        for (int i = 0; i < 4; i++) {
            int idx = t + 256 * i;       // 0..1023
            int r = idx >> 3, c = idx & 7;
            CP_ASYNC16(abase + (uint32_t)(r * LDSH + c * 8) * 2,
                       Ag + (size_t)r * KTOT + c * 8);
            int gr = c0 + r; if (gr > NUM_CLASSES - 1) gr = NUM_CLASSES - 1;
            CP_ASYNC16(bbase + (uint32_t)(r * LDSH + c * 8) * 2,
                       Wg + (size_t)gr * KTOT + k0 + c * 8);
        }
        CP_COMMIT();
    };

    wmma::fragment<wmma::accumulator, 16, 16, 16, float> acc[4][2];
    #pragma unroll
    for (int i = 0; i < 4; i++)
        #pragma unroll
        for (int j = 0; j < 2; j++)
            wmma::fill_fragment(acc[i][j], 0.0f);

    issue(0); issue(1); issue(2);

    #pragma unroll 1
    for (int it = 0; it < NST; it++) {
        if (it <= NST - 3)      CP_WAIT(2);
        else if (it == NST - 2) CP_WAIT(1);
        else                    CP_WAIT(0);
        __syncthreads();

        const __half* As = smem + (it % 3) * (2 * STAGE_ELEMS);
        const __half* Bs = As + STAGE_ELEMS;

        #pragma unroll
        for (int kk = 0; kk < BK / 16; kk++) {
            wmma::fragment<wmma::matrix_b, 16, 16, 16, __half, wmma::col_major> bf[2];
            #pragma unroll
            for (int j = 0; j < 2; j++)
                wmma::load_matrix_sync(bf[j], Bs + (wc * 32 + j * 16) * LDSH + kk * 16, LDSH);
            #pragma unroll
            for (int i = 0; i < 4; i++) {
                wmma::fragment<wmma::matrix_a, 16, 16, 16, __half, wmma::row_major> af;
                wmma::load_matrix_sync(af, As + (wr * 64 + i * 16) * LDSH + kk * 16, LDSH);
                #pragma unroll
                for (int j = 0; j < 2; j++)
                    wmma::mma_sync(acc[i][j], af, bf[j], acc[i][j]);
            }
        }
        __syncthreads();
        issue(it + 3);
    }

    // -------- epilogue: frag -> smem bounce -> coalesced fp32 store + bias --------
    __syncthreads();
    float* cbuf = reinterpret_cast<float*>(smem) + warp * (16 * 20);
    #pragma unroll
    for (int i = 0; i < 4; i++) {
        #pragma unroll
        for (int j = 0; j < 2; j++) {
            wmma::store_matrix_sync(cbuf, acc[i][j], 20, wmma::mem_row_major);
            __syncwarp();
            int mb = b0 + wr * 64 + i * 16;
            int cb = c0 + wc * 32 + j * 16;
            #pragma unroll
            for (int e = 0; e < 8; e++) {
                int idx = lane + 32 * e;     // 0..255
                int rr = idx >> 4, cc = idx & 15;
                int c = cb + cc;
                if (c < NUM_CLASSES)
                    out[(size_t)(mb + rr) * NUM_CLASSES + c] = cbuf[rr * 20 + cc] + __ldg(base_b + c);
            }
            __syncwarp();
        }
    }
}

// ---------------------------------------------------------------------------
extern "C" void kernel_launch(void* const* d_in, const int* in_sizes, int n_in,
                              void* d_out, int out_size)
{
    const float* x       = (const float*)d_in[0];
    const float* context = (const float*)d_in[1];
    const float* base_w  = (const float*)d_in[2];
    const float* base_b  = (const float*)d_in[3];
    const float* ctx_w   = (const float*)d_in[4];
    const float* ctx_b   = (const float*)d_in[5];
    const float* ln_g    = (const float*)d_in[6];
    const float* ln_b    = (const float*)d_in[7];
    const float* coeff_w = (const float*)d_in[8];
    const float* coeff_b = (const float*)d_in[9];
    const float* basis_A = (const float*)d_in[10];
    const float* basis_B = (const float*)d_in[11];
    float* out = (float*)d_out;
    (void)in_sizes; (void)n_in; (void)out_size;

    prep_ctx<<<BATCH / 16, 256>>>(x, context, ctx_w, ctx_b, ln_g, ln_b,
                                  coeff_w, coeff_b, basis_A);
    convert_x<<<(unsigned)(((size_t)BATCH * (KTOT / 8) + 255) / 256), 256>>>(x);
    convert_w<<<(unsigned)(((size_t)NUM_CLASSES * (KTOT / 8) + 255) / 256), 256>>>(base_w, basis_B);

    static_assert(SMEM_TOTAL == 110592, "smem layout");
    cudaFuncSetAttribute(main_gemm, cudaFuncAttributeMaxDynamicSharedMemorySize, SMEM_TOTAL);
    dim3 grid(BATCH / BM, (NUM_CLASSES + BN - 1) / BN);   // 16 x 393, m fastest
    main_gemm<<<grid, 256, SMEM_TOTAL>>>(base_b, out);
}

// round 4
// speedup vs baseline: 2.0345x; 1.5785x over previous
#include <cuda_runtime.h>
#include <cuda_fp16.h>
#include <mma.h>
#include <cstdint>

using namespace nvcuda;

#define D_MODEL     2048
#define NUM_CLASSES 50257
#define NB          8
#define RANK        4
#define HIDDEN      128
#define BATCH       2048
#define LN_EPS      1e-5f

#define KTOT   2112                 // 2048 (x|w) + 32 (LoRA u|Bt) + 32 zero pad
#define BK     64                   // K per pipeline stage
#define NST    (KTOT / BK)          // 33 stages, single fp16 pass

#define BM 128
#define BN 128
#define LDSH 72                     // fp16 elems per smem row (144B)
#define STAGE_ELEMS (128 * LDSH)
#define STAGE_BYTES (STAGE_ELEMS * 2)       // 18432
#define SMEM_TOTAL  (2 * 2 * STAGE_BYTES)   // 73728 B -> 2 CTAs/SM

// ---------------- device scratch ----------------
__device__ float  g_u[BATCH * 32];
__device__ __half g_Xh[(size_t)BATCH       * KTOT];
__device__ __half g_Wh[(size_t)NUM_CLASSES * KTOT];

__device__ __forceinline__ uint32_t smem_u32(const void* p) {
    uint32_t a;
    asm("{ .reg .u64 t; cvta.to.shared.u64 t, %1; cvt.u32.u64 %0, t; }" : "=r"(a) : "l"(p));
    return a;
}
#define CP_ASYNC16(dst, src) \
    asm volatile("cp.async.cg.shared.global [%0], [%1], 16;" :: "r"(dst), "l"(src))
#define CP_COMMIT() asm volatile("cp.async.commit_group;" ::: "memory")
#define CP_WAIT(n)  asm volatile("cp.async.wait_group %0;" :: "n"(n) : "memory")

// ---------------------------------------------------------------------------
// prep_ctx: ctx MLP -> LN -> GELU -> coeffs -> z -> u  (fp32, 16 rows / block)
// ---------------------------------------------------------------------------
__global__ __launch_bounds__(256) void prep_ctx(
    const float* __restrict__ x, const float* __restrict__ context,
    const float* __restrict__ ctx_w, const float* __restrict__ ctx_b,
    const float* __restrict__ ln_g, const float* __restrict__ ln_b,
    const float* __restrict__ coeff_w, const float* __restrict__ coeff_b,
    const float* __restrict__ basis_A)
{
    __shared__ float h_sh[16][HIDDEN];
    __shared__ float coeffs_sh[16][NB];
    __shared__ float y_sh[16][32];
    __shared__ float z_sh[16][RANK];

    const int t  = threadIdx.x;
    const int r0 = blockIdx.x * 16;

    #pragma unroll 1
    for (int i = 0; i < 8; i++) {
        int idx = t + 256 * i;
        int row = idx >> 7, h = idx & 127;
        const float4* cp = reinterpret_cast<const float4*>(context + (size_t)(r0 + row) * D_MODEL);
        const float4* wp = reinterpret_cast<const float4*>(ctx_w + (size_t)h * D_MODEL);
        float a0 = 0.f, a1 = 0.f, a2 = 0.f, a3 = 0.f;
        #pragma unroll 4
        for (int k = 0; k < D_MODEL / 4; k++) {
            float4 a = cp[k]; float4 b = wp[k];
            a0 += a.x * b.x; a1 += a.y * b.y; a2 += a.z * b.z; a3 += a.w * b.w;
        }
        h_sh[row][h] = (a0 + a1) + (a2 + a3) + ctx_b[h];
    }
    __syncthreads();

    {
        const int lane = t & 31, w = t >> 5;
        #pragma unroll
        for (int rr = 0; rr < 2; rr++) {
            int row = w * 2 + rr;
            float v[4]; float s = 0.f;
            #pragma unroll
            for (int j = 0; j < 4; j++) { v[j] = h_sh[row][lane * 4 + j]; s += v[j]; }
            #pragma unroll
            for (int o = 16; o > 0; o >>= 1) s += __shfl_xor_sync(0xffffffffu, s, o);
            float mu = s * (1.0f / HIDDEN);
            float q = 0.f;
            #pragma unroll
            for (int j = 0; j < 4; j++) { float d = v[j] - mu; q += d * d; }
            #pragma unroll
            for (int o = 16; o > 0; o >>= 1) q += __shfl_xor_sync(0xffffffffu, q, o);
            float rstd = rsqrtf(q * (1.0f / HIDDEN) + LN_EPS);
            #pragma unroll
            for (int j = 0; j < 4; j++) {
                int c = lane * 4 + j;
                float hn = (v[j] - mu) * rstd * ln_g[c] + ln_b[c];
                h_sh[row][c] = 0.5f * hn * (1.0f + erff(hn * 0.7071067811865475f));
            }
        }
    }
    __syncthreads();

    if (t < 128) {
        int row = t >> 3, n = t & 7;
        const float* wp = coeff_w + (size_t)n * HIDDEN;
        float acc = coeff_b[n];
        #pragma unroll 8
        for (int j = 0; j < HIDDEN; j++) acc += h_sh[row][j] * wp[j];
        coeffs_sh[row][n] = acc;
    }

    #pragma unroll 1
    for (int i = 0; i < 2; i++) {
        int idx = t + 256 * i;
        int row = idx >> 5, k = idx & 31;
        const float4* xp = reinterpret_cast<const float4*>(x + (size_t)(r0 + row) * D_MODEL);
        const float4* ap = reinterpret_cast<const float4*>(basis_A + (size_t)k * D_MODEL);
        float a0 = 0.f, a1 = 0.f, a2 = 0.f, a3 = 0.f;
        #pragma unroll 4
        for (int kk = 0; kk < D_MODEL / 4; kk++) {
            float4 a = xp[kk]; float4 b = ap[kk];
            a0 += a.x * b.x; a1 += a.y * b.y; a2 += a.z * b.z; a3 += a.w * b.w;
        }
        y_sh[row][k] = (a0 + a1) + (a2 + a3);
    }
    __syncthreads();

    if (t < 64) {
        int row = t >> 2, r = t & 3;
        float acc = 0.f;
        #pragma unroll
        for (int n = 0; n < NB; n++) acc += coeffs_sh[row][n] * y_sh[row][n * RANK + r];
        z_sh[row][r] = acc;
    }
    __syncthreads();

    #pragma unroll
    for (int i = 0; i < 2; i++) {
        int idx = t + 256 * i;
        int row = idx >> 5, k = idx & 31;
        g_u[(size_t)(r0 + row) * 32 + k] = coeffs_sh[row][k >> 2] * z_sh[row][k & 3];
    }
}

// ---------------------------------------------------------------------------
// convert_x: g_Xh[b][0:2048]=fp16(x), [2048:2080]=fp16(u), rest 0
// ---------------------------------------------------------------------------
__global__ __launch_bounds__(256) void convert_x(const float* __restrict__ x)
{
    size_t i = (size_t)blockIdx.x * 256 + threadIdx.x;
    if (i >= (size_t)BATCH * (KTOT / 8)) return;
    int row = (int)(i / (KTOT / 8));
    int k0  = (int)(i % (KTOT / 8)) * 8;

    float v[8];
    if (k0 < D_MODEL) {
        const float4* p = reinterpret_cast<const float4*>(x + (size_t)row * D_MODEL + k0);
        float4 a = p[0], b = p[1];
        v[0]=a.x; v[1]=a.y; v[2]=a.z; v[3]=a.w; v[4]=b.x; v[5]=b.y; v[6]=b.z; v[7]=b.w;
    } else if (k0 < D_MODEL + 32) {
        #pragma unroll
        for (int j = 0; j < 8; j++) v[j] = g_u[(size_t)row * 32 + (k0 - D_MODEL) + j];
    } else {
        #pragma unroll
        for (int j = 0; j < 8; j++) v[j] = 0.f;
    }
    union { __half h[8]; uint4 u; } H;
    #pragma unroll
    for (int j = 0; j < 8; j++) H.h[j] = __float2half_rn(v[j]);
    *reinterpret_cast<uint4*>(&g_Xh[(size_t)row * KTOT + k0]) = H.u;
}

// ---------------------------------------------------------------------------
// convert_w: g_Wh = fp16(w); LoRA Bt appended at k>=2048, zero pad after
// ---------------------------------------------------------------------------
__global__ __launch_bounds__(256) void convert_w(
    const float* __restrict__ base_w, const float* __restrict__ basis_B)
{
    size_t i = (size_t)blockIdx.x * 256 + threadIdx.x;
    if (i >= (size_t)NUM_CLASSES * (KTOT / 8)) return;
    int row = (int)(i / (KTOT / 8));
    int k0  = (int)(i % (KTOT / 8)) * 8;

    float v[8];
    if (k0 < D_MODEL) {
        const float4* p = reinterpret_cast<const float4*>(base_w + (size_t)row * D_MODEL + k0);
        float4 a = p[0], b = p[1];
        v[0]=a.x; v[1]=a.y; v[2]=a.z; v[3]=a.w; v[4]=b.x; v[5]=b.y; v[6]=b.z; v[7]=b.w;
    } else if (k0 < D_MODEL + 32) {
        #pragma unroll
        for (int j = 0; j < 8; j++) {
            int k = (k0 - D_MODEL) + j;      // n*RANK + r
            v[j] = basis_B[(((size_t)(k >> 2)) * NUM_CLASSES + row) * RANK + (k & 3)];
        }
    } else {
        #pragma unroll
        for (int j = 0; j < 8; j++) v[j] = 0.f;
    }
    union { __half h[8]; uint4 u; } H;
    #pragma unroll
    for (int j = 0; j < 8; j++) H.h[j] = __float2half_rn(v[j]);
    *reinterpret_cast<uint4*>(&g_Wh[(size_t)row * KTOT + k0]) = H.u;
}

// ---------------------------------------------------------------------------
// Main GEMM: out[b][c] = Xh[b]·Wh[c] + base_b[c]
// 128x128 tile, 8 warps (64x32 warp tiles), BK=64, 2-stage cp.async pipeline,
// 2 CTAs/SM (73.7 KB smem each).
// ---------------------------------------------------------------------------
__global__ __launch_bounds__(256, 2) void main_gemm(
    const float* __restrict__ base_b, float* __restrict__ out)
{
    extern __shared__ __align__(128) __half smem[];
    const uint32_t sbase = smem_u32(smem);

    const int t    = threadIdx.x;
    const int warp = t >> 5;
    const int lane = t & 31;
    const int b0   = blockIdx.x * BM;
    const int c0   = blockIdx.y * BN;

    const int wr = warp >> 2;   // 0..1 (64 rows)
    const int wc = warp & 3;    // 0..3 (32 cols)

    auto issue = [&](int s) {
        if (s >= NST) return;
        int k0 = s * BK;
        const __half* Ag = g_Xh + (size_t)b0 * KTOT + k0;
        int slot = s & 1;
        uint32_t abase = sbase + slot * (2 * STAGE_BYTES);
        uint32_t bbase = abase + STAGE_BYTES;
        #pragma unroll
        for (int i = 0; i < 4; i++) {
            int idx = t + 256 * i;       // 0..1023
            int r = idx >> 3, c = idx & 7;
            CP_ASYNC16(abase + (uint32_t)(r * LDSH + c * 8) * 2,
                       Ag + (size_t)r * KTOT + c * 8);
            int gr = c0 + r; if (gr > NUM_CLASSES - 1) gr = NUM_CLASSES - 1;
            CP_ASYNC16(bbase + (uint32_t)(r * LDSH + c * 8) * 2,
                       g_Wh + (size_t)gr * KTOT + k0 + c * 8);
        }
        CP_COMMIT();
    };

    wmma::fragment<wmma::accumulator, 16, 16, 16, float> acc[4][2];
    #pragma unroll
    for (int i = 0; i < 4; i++)
        #pragma unroll
        for (int j = 0; j < 2; j++)
            wmma::fill_fragment(acc[i][j], 0.0f);

    issue(0); issue(1);

    #pragma unroll 1
    for (int it = 0; it < NST; it++) {
        if (it < NST - 1) CP_WAIT(1);
        else              CP_WAIT(0);
        __syncthreads();

        const __half* As = smem + (it & 1) * (2 * STAGE_ELEMS);
        const __half* Bs = As + STAGE_ELEMS;

        #pragma unroll
        for (int kk = 0; kk < BK / 16; kk++) {
            wmma::fragment<wmma::matrix_b, 16, 16, 16, __half, wmma::col_major> bf[2];
            #pragma unroll
            for (int j = 0; j < 2; j++)
                wmma::load_matrix_sync(bf[j], Bs + (wc * 32 + j * 16) * LDSH + kk * 16, LDSH);
            #pragma unroll
            for (int i = 0; i < 4; i++) {
                wmma::fragment<wmma::matrix_a, 16, 16, 16, __half, wmma::row_major> af;
                wmma::load_matrix_sync(af, As + (wr * 64 + i * 16) * LDSH + kk * 16, LDSH);
                #pragma unroll
                for (int j = 0; j < 2; j++)
                    wmma::mma_sync(acc[i][j], af, bf[j], acc[i][j]);
            }
        }
        __syncthreads();   // everyone done reading slot before overwriting it
        issue(it + 2);
    }

    // -------- epilogue: frag -> smem bounce -> coalesced fp32 store + bias --------
    __syncthreads();
    float* cbuf = reinterpret_cast<float*>(smem) + warp * (16 * 20);
    #pragma unroll
    for (int i = 0; i < 4; i++) {
        #pragma unroll
        for (int j = 0; j < 2; j++) {
            wmma::store_matrix_sync(cbuf, acc[i][j], 20, wmma::mem_row_major);
            __syncwarp();
            int mb = b0 + wr * 64 + i * 16;
            int cb = c0 + wc * 32 + j * 16;
            #pragma unroll
            for (int e = 0; e < 8; e++) {
                int idx = lane + 32 * e;     // 0..255
                int rr = idx >> 4, cc = idx & 15;
                int c = cb + cc;
                if (c < NUM_CLASSES)
                    out[(size_t)(mb + rr) * NUM_CLASSES + c] = cbuf[rr * 20 + cc] + __ldg(base_b + c);
            }
            __syncwarp();
        }
    }
}

// ---------------------------------------------------------------------------
extern "C" void kernel_launch(void* const* d_in, const int* in_sizes, int n_in,
                              void* d_out, int out_size)
{
    const float* x       = (const float*)d_in[0];
    const float* context = (const float*)d_in[1];
    const float* base_w  = (const float*)d_in[2];
    const float* base_b  = (const float*)d_in[3];
    const float* ctx_w   = (const float*)d_in[4];
    const float* ctx_b   = (const float*)d_in[5];
    const float* ln_g    = (const float*)d_in[6];
    const float* ln_b    = (const float*)d_in[7];
    const float* coeff_w = (const float*)d_in[8];
    const float* coeff_b = (const float*)d_in[9];
    const float* basis_A = (const float*)d_in[10];
    const float* basis_B = (const float*)d_in[11];
    float* out = (float*)d_out;
    (void)in_sizes; (void)n_in; (void)out_size;

    prep_ctx<<<BATCH / 16, 256>>>(x, context, ctx_w, ctx_b, ln_g, ln_b,
                                  coeff_w, coeff_b, basis_A);
    convert_x<<<(unsigned)(((size_t)BATCH * (KTOT / 8) + 255) / 256), 256>>>(x);
    convert_w<<<(unsigned)(((size_t)NUM_CLASSES * (KTOT / 8) + 255) / 256), 256>>>(base_w, basis_B);

    static_assert(SMEM_TOTAL == 73728, "smem layout");
    cudaFuncSetAttribute(main_gemm, cudaFuncAttributeMaxDynamicSharedMemorySize, SMEM_TOTAL);
    dim3 grid(BATCH / BM, (NUM_CLASSES + BN - 1) / BN);   // 16 x 393, m fastest
    main_gemm<<<grid, 256, SMEM_TOTAL>>>(base_b, out);
}

// round 5
// speedup vs baseline: 2.0961x; 1.0302x over previous
#include <cuda_runtime.h>
#include <cuda_fp16.h>
#include <mma.h>
#include <cstdint>

using namespace nvcuda;

#define D_MODEL     2048
#define NUM_CLASSES 50257
#define NB          8
#define RANK        4
#define HIDDEN      128
#define BATCH       2048
#define LN_EPS      1e-5f

#define KTOT   2112                 // 2048 (x|w) + 32 (LoRA u|Bt) + 32 zero pad
#define BK     64
#define NST    (KTOT / BK)          // 33 stages, single fp16 pass

#define BM 128
#define BN 128
#define LDSH 72                     // fp16 elems per smem row (144B)
#define STAGE_ELEMS (128 * LDSH)
#define STAGE_BYTES (STAGE_ELEMS * 2)       // 18432
#define SMEM_TOTAL  (3 * 2 * STAGE_BYTES)   // 110592 B -> 2 CTAs/SM (verified R3)

// prep_ctx dynamic smem layout (floats)
#define P_WSH   0                       // 128*129 (ash aliases first 32*129)
#define P_XSH   (128 * 129)             // 16*129
#define P_HSH   (P_XSH + 16 * 129)      // 16*128
#define P_YSH   (P_HSH + 16 * 128)      // 16*32
#define P_CSH   (P_YSH + 16 * 32)       // 16*8
#define P_ZSH   (P_CSH + 16 * 8)        // 16*4
#define P_TOTAL (P_ZSH + 16 * 4)        // 21328 floats = 85312 B

// ---------------- device scratch ----------------
__device__ float  g_u[BATCH * 32];
__device__ __half g_Xh[(size_t)BATCH       * KTOT];
__device__ __half g_Wh[(size_t)NUM_CLASSES * KTOT];

__device__ __forceinline__ uint32_t smem_u32(const void* p) {
    uint32_t a;
    asm("{ .reg .u64 t; cvta.to.shared.u64 t, %1; cvt.u32.u64 %0, t; }" : "=r"(a) : "l"(p));
    return a;
}
#define CP_ASYNC16(dst, src) \
    asm volatile("cp.async.cg.shared.global [%0], [%1], 16;" :: "r"(dst), "l"(src))
#define CP_COMMIT() asm volatile("cp.async.commit_group;" ::: "memory")
#define CP_WAIT(n)  asm volatile("cp.async.wait_group %0;" :: "n"(n) : "memory")

// ---------------------------------------------------------------------------
// prep_ctx (coalesced): ctx MLP -> LN -> GELU -> coeffs -> z -> u
// 16 batch rows per block, 256 threads, smem-tiled k-coalesced GEMMs.
// ---------------------------------------------------------------------------
__global__ __launch_bounds__(256) void prep_ctx(
    const float* __restrict__ x, const float* __restrict__ context,
    const float* __restrict__ ctx_w, const float* __restrict__ ctx_b,
    const float* __restrict__ ln_g, const float* __restrict__ ln_b,
    const float* __restrict__ coeff_w, const float* __restrict__ coeff_b,
    const float* __restrict__ basis_A)
{
    extern __shared__ float ps[];
    float* wsh = ps + P_WSH;       // [128][129] (Phase A) / ash [32][129] (Phase D)
    float* xsh = ps + P_XSH;       // [16][129]
    float* hsh = ps + P_HSH;       // [16][128]
    float* ysh = ps + P_YSH;       // [16][32]
    float* csh = ps + P_CSH;       // [16][8]
    float* zsh = ps + P_ZSH;       // [16][4]

    const int t  = threadIdx.x;
    const int r0 = blockIdx.x * 16;

    // ---- Phase A: h0 = context @ ctx_w^T + ctx_b, k-tiled in chunks of 128 ----
    {
        const int hA    = t & 127;
        const int rhalf = t >> 7;          // 0/1 -> rows rhalf*8 .. +7
        float acc[8];
        #pragma unroll
        for (int r = 0; r < 8; r++) acc[r] = 0.f;

        #pragma unroll 1
        for (int kc = 0; kc < D_MODEL / 128; kc++) {
            #pragma unroll
            for (int i = 0; i < 16; i++) {                 // ctx_w tile 128x128
                int idx = t + 256 * i;                      // 0..4095 float4s
                int h = idx >> 5, kq = idx & 31;
                float4 v = *reinterpret_cast<const float4*>(
                    ctx_w + (size_t)h * D_MODEL + kc * 128 + kq * 4);
                float* d = wsh + h * 129 + kq * 4;
                d[0] = v.x; d[1] = v.y; d[2] = v.z; d[3] = v.w;
            }
            #pragma unroll
            for (int i = 0; i < 8; i++) {                  // context tile 16x128
                int idx = t + 256 * i;                      // 0..2047
                int r = idx >> 7, k = idx & 127;
                xsh[r * 129 + k] = context[(size_t)(r0 + r) * D_MODEL + kc * 128 + k];
            }
            __syncthreads();
            #pragma unroll 4
            for (int k = 0; k < 128; k++) {
                float w = wsh[hA * 129 + k];
                #pragma unroll
                for (int r = 0; r < 8; r++)
                    acc[r] += xsh[(rhalf * 8 + r) * 129 + k] * w;
            }
            __syncthreads();
        }
        float b = ctx_b[hA];
        #pragma unroll
        for (int r = 0; r < 8; r++)
            hsh[(rhalf * 8 + r) * 128 + hA] = acc[r] + b;
    }
    __syncthreads();

    // ---- Phase B: LayerNorm + exact GELU (one warp per 2 rows) ----
    {
        const int lane = t & 31, w = t >> 5;
        #pragma unroll
        for (int rr = 0; rr < 2; rr++) {
            int row = w * 2 + rr;
            float v[4]; float s = 0.f;
            #pragma unroll
            for (int j = 0; j < 4; j++) { v[j] = hsh[row * 128 + lane * 4 + j]; s += v[j]; }
            #pragma unroll
            for (int o = 16; o > 0; o >>= 1) s += __shfl_xor_sync(0xffffffffu, s, o);
            float mu = s * (1.0f / HIDDEN);
            float q = 0.f;
            #pragma unroll
            for (int j = 0; j < 4; j++) { float d = v[j] - mu; q += d * d; }
            #pragma unroll
            for (int o = 16; o > 0; o >>= 1) q += __shfl_xor_sync(0xffffffffu, q, o);
            float rstd = rsqrtf(q * (1.0f / HIDDEN) + LN_EPS);
            #pragma unroll
            for (int j = 0; j < 4; j++) {
                int c = lane * 4 + j;
                float hn = (v[j] - mu) * rstd * ln_g[c] + ln_b[c];
                hsh[row * 128 + c] = 0.5f * hn * (1.0f + erff(hn * 0.7071067811865475f));
            }
        }
    }
    __syncthreads();

    // ---- Phase C: coeffs = h @ coeff_w^T + coeff_b ----
    if (t < 128) {
        int row = t >> 3, n = t & 7;
        const float* wp = coeff_w + (size_t)n * HIDDEN;
        float acc = coeff_b[n];
        #pragma unroll 8
        for (int j = 0; j < HIDDEN; j++) acc += hsh[row * 128 + j] * wp[j];
        csh[row * 8 + n] = acc;
    }
    __syncthreads();

    // ---- Phase D: y = x @ basis_A^T, k-tiled (ash aliases wsh) ----
    {
        const int ka = t & 31;             // basis row 0..31
        const int rq = t >> 5;             // 0..7 -> rows rq*2, rq*2+1
        float acc0 = 0.f, acc1 = 0.f;

        #pragma unroll 1
        for (int kc = 0; kc < D_MODEL / 128; kc++) {
            #pragma unroll
            for (int i = 0; i < 4; i++) {                  // basis_A tile 32x128
                int idx = t + 256 * i;                      // 0..1023 float4s
                int a = idx >> 5, kq = idx & 31;
                float4 v = *reinterpret_cast<const float4*>(
                    basis_A + (size_t)a * D_MODEL + kc * 128 + kq * 4);
                float* d = wsh + a * 129 + kq * 4;
                d[0] = v.x; d[1] = v.y; d[2] = v.z; d[3] = v.w;
            }
            #pragma unroll
            for (int i = 0; i < 8; i++) {                  // x tile 16x128
                int idx = t + 256 * i;
                int r = idx >> 7, k = idx & 127;
                xsh[r * 129 + k] = x[(size_t)(r0 + r) * D_MODEL + kc * 128 + k];
            }
            __syncthreads();
            #pragma unroll 4
            for (int k = 0; k < 128; k++) {
                float a = wsh[ka * 129 + k];
                acc0 += xsh[(rq * 2 + 0) * 129 + k] * a;
                acc1 += xsh[(rq * 2 + 1) * 129 + k] * a;
            }
            __syncthreads();
        }
        ysh[(rq * 2 + 0) * 32 + ka] = acc0;
        ysh[(rq * 2 + 1) * 32 + ka] = acc1;
    }
    __syncthreads();

    // ---- Phase E: z[row][r] = sum_n coeffs[row][n] * y[row][n*RANK+r] ----
    if (t < 64) {
        int row = t >> 2, r = t & 3;
        float acc = 0.f;
        #pragma unroll
        for (int n = 0; n < NB; n++) acc += csh[row * 8 + n] * ysh[row * 32 + n * RANK + r];
        zsh[row * 4 + r] = acc;
    }
    __syncthreads();

    // ---- Phase F: u -> global ----
    #pragma unroll
    for (int i = 0; i < 2; i++) {
        int idx = t + 256 * i;
        int row = idx >> 5, k = idx & 31;
        g_u[(size_t)(r0 + row) * 32 + k] = csh[row * 8 + (k >> 2)] * zsh[row * 4 + (k & 3)];
    }
}

// ---------------------------------------------------------------------------
// convert_x: g_Xh[b][0:2048]=fp16(x), [2048:2080]=fp16(u), rest 0
// ---------------------------------------------------------------------------
__global__ __launch_bounds__(256) void convert_x(const float* __restrict__ x)
{
    size_t i = (size_t)blockIdx.x * 256 + threadIdx.x;
    if (i >= (size_t)BATCH * (KTOT / 8)) return;
    int row = (int)(i / (KTOT / 8));
    int k0  = (int)(i % (KTOT / 8)) * 8;

    float v[8];
    if (k0 < D_MODEL) {
        const float4* p = reinterpret_cast<const float4*>(x + (size_t)row * D_MODEL + k0);
        float4 a = p[0], b = p[1];
        v[0]=a.x; v[1]=a.y; v[2]=a.z; v[3]=a.w; v[4]=b.x; v[5]=b.y; v[6]=b.z; v[7]=b.w;
    } else if (k0 < D_MODEL + 32) {
        #pragma unroll
        for (int j = 0; j < 8; j++) v[j] = g_u[(size_t)row * 32 + (k0 - D_MODEL) + j];
    } else {
        #pragma unroll
        for (int j = 0; j < 8; j++) v[j] = 0.f;
    }
    union { __half h[8]; uint4 u; } H;
    #pragma unroll
    for (int j = 0; j < 8; j++) H.h[j] = __float2half_rn(v[j]);
    *reinterpret_cast<uint4*>(&g_Xh[(size_t)row * KTOT + k0]) = H.u;
}

// ---------------------------------------------------------------------------
// convert_w: g_Wh = fp16(w); LoRA Bt appended at k>=2048, zero pad after
// ---------------------------------------------------------------------------
__global__ __launch_bounds__(256) void convert_w(
    const float* __restrict__ base_w, const float* __restrict__ basis_B)
{
    size_t i = (size_t)blockIdx.x * 256 + threadIdx.x;
    if (i >= (size_t)NUM_CLASSES * (KTOT / 8)) return;
    int row = (int)(i / (KTOT / 8));
    int k0  = (int)(i % (KTOT / 8)) * 8;

    float v[8];
    if (k0 < D_MODEL) {
        const float4* p = reinterpret_cast<const float4*>(base_w + (size_t)row * D_MODEL + k0);
        float4 a = p[0], b = p[1];
        v[0]=a.x; v[1]=a.y; v[2]=a.z; v[3]=a.w; v[4]=b.x; v[5]=b.y; v[6]=b.z; v[7]=b.w;
    } else if (k0 < D_MODEL + 32) {
        #pragma unroll
        for (int j = 0; j < 8; j++) {
            int k = (k0 - D_MODEL) + j;      // n*RANK + r
            v[j] = basis_B[(((size_t)(k >> 2)) * NUM_CLASSES + row) * RANK + (k & 3)];
        }
    } else {
        #pragma unroll
        for (int j = 0; j < 8; j++) v[j] = 0.f;
    }
    union { __half h[8]; uint4 u; } H;
    #pragma unroll
    for (int j = 0; j < 8; j++) H.h[j] = __float2half_rn(v[j]);
    *reinterpret_cast<uint4*>(&g_Wh[(size_t)row * KTOT + k0]) = H.u;
}

// ---------------------------------------------------------------------------
// Main GEMM: out[b][c] = Xh[b]·Wh[c] + base_b[c]
// 128x128 tile, 8 warps (64x32), BK=64, 3-stage cp.async, ONE sync per stage.
// ---------------------------------------------------------------------------
__global__ __launch_bounds__(256, 2) void main_gemm(
    const float* __restrict__ base_b, float* __restrict__ out)
{
    extern __shared__ __align__(128) __half smem[];
    const uint32_t sbase = smem_u32(smem);

    const int t    = threadIdx.x;
    const int warp = t >> 5;
    const int lane = t & 31;
    const int b0   = blockIdx.x * BM;
    const int c0   = blockIdx.y * BN;

    const int wr = warp >> 2;   // 0..1 (64 rows)
    const int wc = warp & 3;    // 0..3 (32 cols)

    auto issue = [&](int s) {
        if (s < NST) {
            int k0 = s * BK;
            const __half* Ag = g_Xh + (size_t)b0 * KTOT + k0;
            int slot = s % 3;
            uint32_t abase = sbase + slot * (2 * STAGE_BYTES);
            uint32_t bbase = abase + STAGE_BYTES;
            #pragma unroll
            for (int i = 0; i < 4; i++) {
                int idx = t + 256 * i;       // 0..1023
                int r = idx >> 3, c = idx & 7;
                CP_ASYNC16(abase + (uint32_t)(r * LDSH + c * 8) * 2,
                           Ag + (size_t)r * KTOT + c * 8);
                int gr = c0 + r; if (gr > NUM_CLASSES - 1) gr = NUM_CLASSES - 1;
                CP_ASYNC16(bbase + (uint32_t)(r * LDSH + c * 8) * 2,
                           g_Wh + (size_t)gr * KTOT + k0 + c * 8);
            }
        }
        CP_COMMIT();   // unconditional: keeps group numbering aligned with stage index
    };

    wmma::fragment<wmma::accumulator, 16, 16, 16, float> acc[4][2];
    #pragma unroll
    for (int i = 0; i < 4; i++)
        #pragma unroll
        for (int j = 0; j < 2; j++)
            wmma::fill_fragment(acc[i][j], 0.0f);

    issue(0); issue(1);

    #pragma unroll 1
    for (int it = 0; it < NST; it++) {
        CP_WAIT(1);            // group `it` complete (<=1 group pending)
        __syncthreads();       // also: all warps done reading slot (it-1)%3
        issue(it + 2);         // writes slot (it+2)%3 == (it-1)%3 — safe post-sync

        const __half* As = smem + (it % 3) * (2 * STAGE_ELEMS);
        const __half* Bs = As + STAGE_ELEMS;

        #pragma unroll
        for (int kk = 0; kk < BK / 16; kk++) {
            wmma::fragment<wmma::matrix_b, 16, 16, 16, __half, wmma::col_major> bf[2];
            #pragma unroll
            for (int j = 0; j < 2; j++)
                wmma::load_matrix_sync(bf[j], Bs + (wc * 32 + j * 16) * LDSH + kk * 16, LDSH);
            #pragma unroll
            for (int i = 0; i < 4; i++) {
                wmma::fragment<wmma::matrix_a, 16, 16, 16, __half, wmma::row_major> af;
                wmma::load_matrix_sync(af, As + (wr * 64 + i * 16) * LDSH + kk * 16, LDSH);
                #pragma unroll
                for (int j = 0; j < 2; j++)
                    wmma::mma_sync(acc[i][j], af, bf[j], acc[i][j]);
            }
        }
    }

    // -------- epilogue: frag -> smem bounce -> coalesced fp32 store + bias --------
    __syncthreads();
    float* cbuf = reinterpret_cast<float*>(smem) + warp * (16 * 20);
    #pragma unroll
    for (int i = 0; i < 4; i++) {
        #pragma unroll
        for (int j = 0; j < 2; j++) {
            wmma::store_matrix_sync(cbuf, acc[i][j], 20, wmma::mem_row_major);
            __syncwarp();
            int mb = b0 + wr * 64 + i * 16;
            int cb = c0 + wc * 32 + j * 16;
            #pragma unroll
            for (int e = 0; e < 8; e++) {
                int idx = lane + 32 * e;     // 0..255
                int rr = idx >> 4, cc = idx & 15;
                int c = cb + cc;
                if (c < NUM_CLASSES)
                    out[(size_t)(mb + rr) * NUM_CLASSES + c] = cbuf[rr * 20 + cc] + __ldg(base_b + c);
            }
            __syncwarp();
        }
    }
}

// ---------------------------------------------------------------------------
extern "C" void kernel_launch(void* const* d_in, const int* in_sizes, int n_in,
                              void* d_out, int out_size)
{
    const float* x       = (const float*)d_in[0];
    const float* context = (const float*)d_in[1];
    const float* base_w  = (const float*)d_in[2];
    const float* base_b  = (const float*)d_in[3];
    const float* ctx_w   = (const float*)d_in[4];
    const float* ctx_b   = (const float*)d_in[5];
    const float* ln_g    = (const float*)d_in[6];
    const float* ln_b    = (const float*)d_in[7];
    const float* coeff_w = (const float*)d_in[8];
    const float* coeff_b = (const float*)d_in[9];
    const float* basis_A = (const float*)d_in[10];
    const float* basis_B = (const float*)d_in[11];
    float* out = (float*)d_out;
    (void)in_sizes; (void)n_in; (void)out_size;

    cudaFuncSetAttribute(prep_ctx, cudaFuncAttributeMaxDynamicSharedMemorySize,
                         P_TOTAL * 4);
    prep_ctx<<<BATCH / 16, 256, P_TOTAL * 4>>>(x, context, ctx_w, ctx_b, ln_g, ln_b,
                                               coeff_w, coeff_b, basis_A);
    convert_x<<<(unsigned)(((size_t)BATCH * (KTOT / 8) + 255) / 256), 256>>>(x);
    convert_w<<<(unsigned)(((size_t)NUM_CLASSES * (KTOT / 8) + 255) / 256), 256>>>(base_w, basis_B);

    static_assert(SMEM_TOTAL == 110592, "smem layout");
    cudaFuncSetAttribute(main_gemm, cudaFuncAttributeMaxDynamicSharedMemorySize, SMEM_TOTAL);
    dim3 grid(BATCH / BM, (NUM_CLASSES + BN - 1) / BN);   // 16 x 393, m fastest
    main_gemm<<<grid, 256, SMEM_TOTAL>>>(base_b, out);
}